// round 8
// baseline (speedup 1.0000x reference)
#include <cuda_runtime.h>

// 7-DOF forward kinematics. R8: R7's folded math + warp-private smem input
// staging: 56 contiguous LDG.128 per warp (4 wf each) replace 7 stride-7
// scalar LDGs (7 wf each). __syncwarp only - no block barrier.

#define DEG 0.017453292519943295f

__global__ void __launch_bounds__(256) fk_kernel(
    const float* __restrict__ thetas,   // [B, 7]
    float* __restrict__ out,            // [B*3 points][B*3 vectors]
    int n)
{
    __shared__ float4 stage[8][56];     // per-warp 224 floats (7168 B)

    int warp = threadIdx.x >> 5;
    int lane = threadIdx.x & 31;
    int wbase = (blockIdx.x * 8 + warp) * 32;   // warp's first element
    int i = wbase + lane;

    float th0, th1, th2, th3, th4, th5, th6;

    if (wbase + 32 <= n) {
        // Warp-cooperative staging: floats [wbase*7, wbase*7+224) as 56 float4
        const float4* g4 = (const float4*)(thetas + wbase * 7);
        stage[warp][lane] = g4[lane];
        if (lane < 24) stage[warp][32 + lane] = g4[32 + lane];
        __syncwarp();
        const float* t = (const float*)stage[warp] + lane * 7;  // conflict-free
        th0 = t[0]; th1 = t[1]; th2 = t[2]; th3 = t[3];
        th4 = t[4]; th5 = t[5]; th6 = t[6];
    } else {
        if (i >= n) return;
        const float* t = thetas + i * 7;
        th0 = t[0]; th1 = t[1]; th2 = t[2]; th3 = t[3];
        th4 = t[4]; th5 = t[5]; th6 = t[6];
    }

    float r0 = th0 * DEG;
    float r1 = th1 * DEG;
    float r2 = th2 * DEG;
    float r3 = th3 * DEG;
    float r4 = th4 * (-0.5f * DEG);
    float r5 = fmaf(th5, DEG / 4.5f, 10.0f * DEG);
    float r6 = fmaf(th6, DEG / 4.5f, 60.0f * DEG);

    float s0, c0, s1, c1, s2, c2, s3, c3, s4, c4, s5, c5, s6, c6;
    __sincosf(r0, &s0, &c0);
    __sincosf(r1, &s1, &c1);
    __sincosf(r2, &s2, &c2);
    __sincosf(r3, &s3, &c3);
    __sincosf(r4, &s4, &c4);
    __sincosf(r5, &s5, &c5);
    __sincosf(r6, &s6, &c6);

    // ---- hand-folded chain (identical to R7, verified) ----
    float A  = fmaf(6.f, c6, 6.f);
    float Bq = fmaf(6.f, s6, -1.f);
    float p5x = s5 * A + c5 * Bq;
    float p5y = s5 * Bq - c5 * A;
    float s56 = s5 * c6 + c5 * s6;
    float c56 = c5 * c6 - s5 * s6;
    float X  = 20.f - p5y;
    float Y  = s4 * p5x;
    float vY = s4 * s56;
    float p11x = -c3 * X - s3 * Y;
    float p11y =  s3 * X - c3 * Y;
    float v11x = -c3 * c56 - s3 * vY;
    float v11y =  s3 * c56 - c3 * vY;
    float p12y = c4 * p5x;
    float v12y = c4 * s56;
    float p13x = p11x + 17.5f;
    float p14x = c2 * p13x + s2 * p12y;
    float p14y = c2 * p12y - s2 * p13x;
    float v14x = c2 * v11x + s2 * v12y;
    float v14y = c2 * v12y - s2 * v11x;
    float p16x = p14x + 3.f;
    float p16z = 9.5f - p14y;
    float p17x = c1 * p16x - s1 * p11y;
    float p17y = s1 * p16x + c1 * p11y;
    float v17x = c1 * v14x - s1 * v11y;
    float v17y = s1 * v14x + c1 * v11y;
    float p19y = p17y - 1.5f;
    float p19z = 2.5f - p17x;
    float px = -s0 * p16z - c0 * p19y;
    float py =  c0 * p16z - s0 * p19y + 5.f;
    float pz = p19z + 19.5f;
    float vx =  s0 * v14y - c0 * v17y;
    float vy = -c0 * v14y - s0 * v17y;
    float vz = -v17x;

    int base = i * 3;
    out[base + 0] = px;
    out[base + 1] = py;
    out[base + 2] = pz;
    int vbase = n * 3 + base;
    out[vbase + 0] = vx;
    out[vbase + 1] = vy;
    out[vbase + 2] = vz;
}

extern "C" void kernel_launch(void* const* d_in, const int* in_sizes, int n_in,
                              void* d_out, int out_size)
{
    const float* thetas = (const float*)d_in[0];
    float* out = (float*)d_out;
    int n = in_sizes[0] / 7;   // B
    int threads = 256;
    int blocks = (n + threads - 1) / threads;
    fk_kernel<<<blocks, threads>>>(thetas, out, n);
}